// round 4
// baseline (speedup 1.0000x reference)
#include <cuda_runtime.h>
#include <math.h>

#define SEQn 2048
#define Dn   768
#define Hn   8
#define DQKn 128
#define DVn  192
#define NQKVn 1344   /* 8*128 + 128 + 192 */
#define NPn  256
#define DPn  128
#define FFIn 1536
#define DPIn 256
#define EPS_RMS 1.1920929e-07f
#define EPS_LN  1e-5f

/* ---------------- scratch (device globals; no allocation) ---------------- */
__device__ float g_xn[SEQn * Dn];
__device__ float g_qkv[SEQn * NQKVn];
__device__ float g_q[Hn * SEQn * DQKn];
__device__ float g_k[SEQn * DQKn];
__device__ float g_v[SEQn * DVn];
__device__ float g_pb[Hn * NPn * NPn];
__device__ float g_ao[SEQn * Hn * DVn];                /* 2048 x 1536 */
__device__ float g_t1[SEQn * FFIn];
__device__ float g_pxn[NPn * NPn * DPn];
__device__ float g_pqk[NPn * NPn * 2 * DPn];
__device__ float g_pv[NPn * NPn * DPn];
__device__ float g_psim[(size_t)NPn * NPn * NPn];      /* 67 MB */
__device__ float g_pt[NPn * NPn * DPIn];
__device__ float g_pt2[NPn * NPn * DPn];

/* ---------------- reductions ---------------- */
template <int OP>  /* 0 = sum, 1 = max */
__device__ __forceinline__ float blockReduce(float v) {
    __shared__ float s[33];
    int lane = threadIdx.x & 31, wid = threadIdx.x >> 5;
#pragma unroll
    for (int o = 16; o > 0; o >>= 1) {
        float ov = __shfl_down_sync(0xffffffffu, v, o);
        v = (OP == 0) ? (v + ov) : fmaxf(v, ov);
    }
    if (lane == 0) s[wid] = v;
    __syncthreads();
    if (threadIdx.x == 0) {
        int nw = (blockDim.x + 31) >> 5;
        float r = s[0];
        for (int i = 1; i < nw; i++) r = (OP == 0) ? (r + s[i]) : fmaxf(r, s[i]);
        s[32] = r;
    }
    __syncthreads();
    float r = s[32];
    __syncthreads();
    return r;
}

/* ---------------- 128x128x8 double-buffered SGEMM: C = A@B (or A@B^T) -----
   requires M % 128 == 0, K % 8 == 0 (N guarded against tile OOB).
   A row-major [M,K]; B row-major [K,N] (TB=false) or [N,K] (TB=true).      */
template <bool TB>
__global__ __launch_bounds__(256) void gemm128_kernel(
    int M, int N, int K,
    const float* __restrict__ A, int lda, long long sA,
    const float* __restrict__ B, int ldb, long long sB,
    float* __restrict__ C, int ldc, long long sC,
    const float* __restrict__ bias, int act)
{
    __shared__ float As[2][8][128];
    __shared__ float Bs[2][8][128];
    int batch = blockIdx.z;
    A += (long long)batch * sA;
    B += (long long)batch * sB;
    C += (long long)batch * sC;
    const int bm = blockIdx.y * 128, bn = blockIdx.x * 128;
    const int tid = threadIdx.x;
    const int tx = tid & 15, ty = tid >> 4;

    const int arow = tid >> 1, akq = (tid & 1) * 4;
    const float* Aptr = A + (long long)(bm + arow) * lda + akq;

    const int brow = tid >> 1, bkq = (tid & 1) * 4;   /* TB: n-row, k-quad  */
    const int bkr = tid >> 5, bnq = (tid & 31) * 4;   /* !TB: k-row, n-quad */
    const bool bvalid = TB ? (bn + brow < N) : (bn + bnq < N);
    const float4 f0 = make_float4(0.f, 0.f, 0.f, 0.f);

    float4 aReg, bReg;
    aReg = *(const float4*)(Aptr);
    if (TB)  bReg = bvalid ? *(const float4*)(B + (long long)(bn + brow) * ldb + bkq) : f0;
    else     bReg = bvalid ? *(const float4*)(B + (long long)bkr * ldb + bn + bnq)    : f0;

    As[0][akq + 0][arow] = aReg.x;
    As[0][akq + 1][arow] = aReg.y;
    As[0][akq + 2][arow] = aReg.z;
    As[0][akq + 3][arow] = aReg.w;
    if (TB) {
        Bs[0][bkq + 0][brow] = bReg.x;
        Bs[0][bkq + 1][brow] = bReg.y;
        Bs[0][bkq + 2][brow] = bReg.z;
        Bs[0][bkq + 3][brow] = bReg.w;
    } else {
        *(float4*)&Bs[0][bkr][bnq] = bReg;
    }
    __syncthreads();

    float acc[8][8];
#pragma unroll
    for (int i = 0; i < 8; i++)
#pragma unroll
        for (int j = 0; j < 8; j++) acc[i][j] = 0.f;

    const int nt = K >> 3;
    int buf = 0;
    for (int kt = 0; kt < nt; kt++) {
        if (kt + 1 < nt) {
            int k0 = (kt + 1) << 3;
            aReg = *(const float4*)(Aptr + k0);
            if (TB)  bReg = bvalid ? *(const float4*)(B + (long long)(bn + brow) * ldb + k0 + bkq) : f0;
            else     bReg = bvalid ? *(const float4*)(B + (long long)(k0 + bkr) * ldb + bn + bnq)  : f0;
        }
#pragma unroll
        for (int kk = 0; kk < 8; kk++) {
            float a[8], b[8];
            *(float4*)&a[0] = *(const float4*)&As[buf][kk][ty * 4];
            *(float4*)&a[4] = *(const float4*)&As[buf][kk][64 + ty * 4];
            *(float4*)&b[0] = *(const float4*)&Bs[buf][kk][tx * 4];
            *(float4*)&b[4] = *(const float4*)&Bs[buf][kk][64 + tx * 4];
#pragma unroll
            for (int i = 0; i < 8; i++)
#pragma unroll
                for (int j = 0; j < 8; j++) acc[i][j] = fmaf(a[i], b[j], acc[i][j]);
        }
        if (kt + 1 < nt) {
            buf ^= 1;
            As[buf][akq + 0][arow] = aReg.x;
            As[buf][akq + 1][arow] = aReg.y;
            As[buf][akq + 2][arow] = aReg.z;
            As[buf][akq + 3][arow] = aReg.w;
            if (TB) {
                Bs[buf][bkq + 0][brow] = bReg.x;
                Bs[buf][bkq + 1][brow] = bReg.y;
                Bs[buf][bkq + 2][brow] = bReg.z;
                Bs[buf][bkq + 3][brow] = bReg.w;
            } else {
                *(float4*)&Bs[buf][bkr][bnq] = bReg;
            }
        }
        __syncthreads();
    }

#pragma unroll
    for (int ih = 0; ih < 2; ih++) {
#pragma unroll
        for (int ii = 0; ii < 4; ii++) {
            int m = bm + ih * 64 + ty * 4 + ii;
#pragma unroll
            for (int jh = 0; jh < 2; jh++) {
                int n = bn + jh * 64 + tx * 4;
                if (n < N) {
                    float4 v;
                    v.x = acc[ih * 4 + ii][jh * 4 + 0];
                    v.y = acc[ih * 4 + ii][jh * 4 + 1];
                    v.z = acc[ih * 4 + ii][jh * 4 + 2];
                    v.w = acc[ih * 4 + ii][jh * 4 + 3];
                    if (bias) {
                        v.x += bias[n + 0]; v.y += bias[n + 1];
                        v.z += bias[n + 2]; v.w += bias[n + 3];
                    }
                    if (act == 1) {
                        v.x = fmaxf(v.x, 0.f); v.y = fmaxf(v.y, 0.f);
                        v.z = fmaxf(v.z, 0.f); v.w = fmaxf(v.w, 0.f);
                    }
                    *(float4*)&C[(long long)m * ldc + n] = v;
                }
            }
        }
    }
}

/* ---------------- fused flash attention (single track) --------------------
   grid (SEQ/64, H), 256 threads. Softclamp bounds logits to [-5,5] so the
   softmax needs NO max subtraction: accumulate exp and row-sums directly.   */
#define FA_SMEM (128*64*2 + 64*192 + 64*68)   /* floats */
__global__ __launch_bounds__(256) void flash_attn_k(
    const float* __restrict__ qg,   /* [H][SEQ][128] */
    const float* __restrict__ kg,   /* [SEQ][128]    */
    const float* __restrict__ vg,   /* [SEQ][192]    */
    const float* __restrict__ pbg,  /* [H][256][256] */
    float* __restrict__ ao)         /* [SEQ][H*192]  */
{
    extern __shared__ float sm[];
    float* Qt = sm;                 /* [128][64] transposed */
    float* Kt = Qt + 128 * 64;      /* [128][64] transposed */
    float* Vs = Kt + 128 * 64;      /* [64][192]            */
    float* Ps = Vs + 64 * 192;      /* [64][68]  padded     */
    const int h = blockIdx.y;
    const int q0 = blockIdx.x * 64;
    const int tid = threadIdx.x;
    const int tx = tid & 15, ty = tid >> 4;

    /* load Q tile transposed */
    {
        const int row = tid >> 2, kq = tid & 3;
        const float* src = qg + ((size_t)h * SEQn + q0 + row) * DQKn;
#pragma unroll
        for (int i = 0; i < 8; i++) {
            int kk = (kq + i * 4) * 4;
            float4 t = *(const float4*)(src + kk);
            Qt[(kk + 0) * 64 + row] = t.x;
            Qt[(kk + 1) * 64 + row] = t.y;
            Qt[(kk + 2) * 64 + row] = t.z;
            Qt[(kk + 3) * 64 + row] = t.w;
        }
    }

    float o[4][12];
#pragma unroll
    for (int i = 0; i < 4; i++)
#pragma unroll
        for (int j = 0; j < 12; j++) o[i][j] = 0.f;
    float rsum[4] = {0.f, 0.f, 0.f, 0.f};
    const float* pbh = pbg + (size_t)h * NPn * NPn;

    for (int j0 = 0; j0 < SEQn; j0 += 64) {
        __syncthreads();
        /* load K tile transposed + V tile */
        {
            const int row = tid >> 2, kq = tid & 3;
            const float* src = kg + (size_t)(j0 + row) * DQKn;
#pragma unroll
            for (int i = 0; i < 8; i++) {
                int kk = (kq + i * 4) * 4;
                float4 t = *(const float4*)(src + kk);
                Kt[(kk + 0) * 64 + row] = t.x;
                Kt[(kk + 1) * 64 + row] = t.y;
                Kt[(kk + 2) * 64 + row] = t.z;
                Kt[(kk + 3) * 64 + row] = t.w;
            }
        }
#pragma unroll
        for (int i = 0; i < 12; i++) {
            int fi = tid + i * 256;            /* 3072 float4 total */
            int row = fi / 48, c4 = fi % 48;
            *(float4*)&Vs[row * 192 + c4 * 4] =
                *(const float4*)(vg + (size_t)(j0 + row) * DVn + c4 * 4);
        }
        __syncthreads();

        /* S = Q K^T  (64x64 tile, 16x16 threads x 4x4) */
        float s[4][4];
#pragma unroll
        for (int i = 0; i < 4; i++)
#pragma unroll
            for (int j = 0; j < 4; j++) s[i][j] = 0.f;
#pragma unroll 4
        for (int k = 0; k < 128; k++) {
            float4 a = *(const float4*)&Qt[k * 64 + ty * 4];
            float4 b = *(const float4*)&Kt[k * 64 + tx * 4];
            const float av[4] = {a.x, a.y, a.z, a.w};
            const float bv[4] = {b.x, b.y, b.z, b.w};
#pragma unroll
            for (int i = 0; i < 4; i++)
#pragma unroll
                for (int j = 0; j < 4; j++) s[i][j] = fmaf(av[i], bv[j], s[i][j]);
        }

        /* epilogue: bias + softclamp + exp -> Ps, accumulate row sums */
#pragma unroll
        for (int i = 0; i < 4; i++) {
            int gr = q0 + ty * 4 + i;
            const float* pbr = pbh + (size_t)(gr >> 3) * NPn;
            float4 pv4;
            float* pp = (float*)&pv4;
#pragma unroll
            for (int j = 0; j < 4; j++) {
                int gc = j0 + tx * 4 + j;
                float x = s[i][j] + pbr[gc >> 3];
                /* 5*tanh(x/5), overflow-safe */
                float t = __expf(-0.4f * fabsf(x));
                float th = (1.f - t) / (1.f + t);
                float c = copysignf(5.f * th, x);
                float p = __expf(c);
                rsum[i] += p;
                pp[j] = p;
            }
            *(float4*)&Ps[(ty * 4 + i) * 68 + tx * 4] = pv4;
        }
        __syncthreads();

        /* O += P V  (64x192 tile, 16x16 threads x 4x12) */
#pragma unroll 2
        for (int k = 0; k < 64; k++) {
            float a0 = Ps[(ty * 4 + 0) * 68 + k];
            float a1 = Ps[(ty * 4 + 1) * 68 + k];
            float a2 = Ps[(ty * 4 + 2) * 68 + k];
            float a3 = Ps[(ty * 4 + 3) * 68 + k];
            const float* vr = &Vs[k * 192 + tx * 12];
            float4 v0 = *(const float4*)(vr);
            float4 v1 = *(const float4*)(vr + 4);
            float4 v2 = *(const float4*)(vr + 8);
            const float vv[12] = {v0.x, v0.y, v0.z, v0.w,
                                  v1.x, v1.y, v1.z, v1.w,
                                  v2.x, v2.y, v2.z, v2.w};
            const float aa[4] = {a0, a1, a2, a3};
#pragma unroll
            for (int i = 0; i < 4; i++)
#pragma unroll
                for (int j = 0; j < 12; j++) o[i][j] = fmaf(aa[i], vv[j], o[i][j]);
        }
    }

    /* reduce row sums across the 16 tx lanes (xor stays inside warp) */
#pragma unroll
    for (int off = 1; off < 16; off <<= 1)
#pragma unroll
        for (int i = 0; i < 4; i++)
            rsum[i] += __shfl_xor_sync(0xffffffffu, rsum[i], off);

#pragma unroll
    for (int i = 0; i < 4; i++) {
        float inv = 1.f / rsum[i];
        int gr = q0 + ty * 4 + i;
        float* dst = ao + (size_t)gr * (Hn * DVn) + h * DVn + tx * 12;
        float4 w0, w1, w2;
        w0.x = o[i][0] * inv;  w0.y = o[i][1] * inv;
        w0.z = o[i][2] * inv;  w0.w = o[i][3] * inv;
        w1.x = o[i][4] * inv;  w1.y = o[i][5] * inv;
        w1.z = o[i][6] * inv;  w1.w = o[i][7] * inv;
        w2.x = o[i][8] * inv;  w2.y = o[i][9] * inv;
        w2.z = o[i][10] * inv; w2.w = o[i][11] * inv;
        *(float4*)(dst) = w0;
        *(float4*)(dst + 4) = w1;
        *(float4*)(dst + 8) = w2;
    }
}

/* ---------------- norms ---------------- */
__global__ void rmsnorm_k(const float* __restrict__ x, const float* __restrict__ w,
                          float* __restrict__ y, int cols)
{
    long long r = blockIdx.x;
    const float* xr = x + r * cols;
    float ss = 0.f;
    for (int c = threadIdx.x; c < cols; c += blockDim.x) { float v = xr[c]; ss += v * v; }
    ss = blockReduce<0>(ss);
    float inv = rsqrtf(ss / cols + EPS_RMS);
    for (int c = threadIdx.x; c < cols; c += blockDim.x)
        y[r * cols + c] = xr[c] * inv * w[c];
}

__global__ void rmsnorm_add_k(const float* __restrict__ x, const float* __restrict__ w,
                              float* __restrict__ res, int cols)
{
    long long r = blockIdx.x;
    const float* xr = x + r * cols;
    float ss = 0.f;
    for (int c = threadIdx.x; c < cols; c += blockDim.x) { float v = xr[c]; ss += v * v; }
    ss = blockReduce<0>(ss);
    float inv = rsqrtf(ss / cols + EPS_RMS);
    for (int c = threadIdx.x; c < cols; c += blockDim.x)
        res[r * cols + c] += xr[c] * inv * w[c];
}

__global__ void add_k(float* __restrict__ a, const float* __restrict__ b, long long n)
{
    long long i = (long long)blockIdx.x * blockDim.x + threadIdx.x;
    if (i < n) a[i] += b[i];
}

/* ---------------- qkv post: per-head LayerNorm + scale + rotary ---------------- */
__global__ void qkv_post_k(const float* __restrict__ qkv,
                           const float* __restrict__ qn, const float* __restrict__ kn,
                           const float* __restrict__ vn,
                           float* __restrict__ q, float* __restrict__ k, float* __restrict__ v)
{
    int n = blockIdx.x, s = blockIdx.y, t = threadIdx.x;
    int len = (s == 9) ? 192 : 128;
    int off = (s < 8) ? s * 128 : (s == 8 ? 1024 : 1152);
    __shared__ float xs[192];
    float x = 0.f;
    if (t < len) x = qkv[(long long)n * NQKVn + off + t];
    float sum = blockReduce<0>(t < len ? x : 0.f);
    float sq  = blockReduce<0>(t < len ? x * x : 0.f);
    float mu = sum / len;
    float var = sq / len - mu * mu;
    float inv = rsqrtf(var + EPS_LN);
    float y = 0.f;
    if (t < len) {
        const float* w = (s < 8) ? qn : (s == 8 ? kn : vn);
        y = (x - mu) * inv * w[t];
        if (s < 8) y *= 0.125f;  /* SCALE = 64^-0.5 */
    }
    if (s == 9) { if (t < 192) v[n * DVn + t] = y; return; }
    /* rotary: fp32 inv_freq -> only dims {0,64} rotate with freq 0.1 */
    xs[t] = y;
    __syncthreads();
    if (t < 128) {
        int d2 = t & 63;
        float invf = (d2 == 0) ? 0.1f : 0.0f;
        float f = (float)n * invf;
        float c = cosf(f), si = sinf(f);
        float rh = (t < 64) ? -xs[t + 64] : xs[t - 64];
        float out = y * c + rh * si;
        if (s < 8) q[((size_t)s * SEQn + n) * DQKn + t] = out;
        else       k[n * DQKn + t] = out;
    }
}

/* ---------------- pairwise bias projection: rms -> gelu -> [128->8] ---------------- */
__global__ void pb_kernel(const float* __restrict__ pair, const float* __restrict__ rw,
                          const float* __restrict__ proj, float* __restrict__ pb)
{
    int ij = blockIdx.x, t = threadIdx.x;  /* 128 threads */
    float x = pair[(long long)ij * DPn + t];
    float ms = blockReduce<0>(x * x) * (1.f / DPn);
    float y = x * rsqrtf(ms + EPS_RMS) * rw[t];
    float g = 0.5f * y * (1.f + erff(y * 0.70710678118654752f));
    float p[8];
#pragma unroll
    for (int h = 0; h < 8; h++) p[h] = g * proj[t * 8 + h];
    __shared__ float sh[8][4];
    int lane = t & 31, wid = t >> 5;
#pragma unroll
    for (int h = 0; h < 8; h++) {
        float v = p[h];
        for (int o = 16; o > 0; o >>= 1) v += __shfl_down_sync(0xffffffffu, v, o);
        if (lane == 0) sh[h][wid] = v;
    }
    __syncthreads();
    if (t < 8) {
        float v = sh[t][0] + sh[t][1] + sh[t][2] + sh[t][3];
        int i = ij >> 8, j = ij & 255;
        pb[((t * NPn) + i) * NPn + j] = v;
    }
}

/* ---------------- pairwise softmax (rows of 256) ---------------- */
__global__ void softmax_p_k(float* __restrict__ psim)
{
    long long r = blockIdx.x;
    float* row = psim + r * NPn;
    float x = row[threadIdx.x];
    float mx = blockReduce<1>(x);
    float e = __expf(x - mx);
    float s = blockReduce<0>(e);
    row[threadIdx.x] = e / s;
}

/* ---------------- host helpers ---------------- */
static inline void launch_gemm(bool tb, int M, int N, int K,
                               const float* A, int lda, long long sA,
                               const float* B, int ldb, long long sB,
                               float* C, int ldc, long long sC, int batch,
                               const float* bias, int act)
{
    dim3 g((N + 127) / 128, M / 128, batch), b(256);
    if (tb) gemm128_kernel<true ><<<g, b>>>(M, N, K, A, lda, sA, B, ldb, sB, C, ldc, sC, bias, act);
    else    gemm128_kernel<false><<<g, b>>>(M, N, K, A, lda, sA, B, ldb, sB, C, ldc, sC, bias, act);
}

extern "C" void kernel_launch(void* const* d_in, const int* in_sizes, int n_in,
                              void* d_out, int out_size)
{
    (void)in_sizes; (void)n_in; (void)out_size;
    const float* in_single = (const float*)d_in[0];
    const float* in_pair   = (const float*)d_in[1];
    const float* W_attn_pre  = (const float*)d_in[2];
    const float* W_attn_post = (const float*)d_in[3];
    const float* W_qkv  = (const float*)d_in[4];
    const float* W_qn   = (const float*)d_in[5];
    const float* W_kn   = (const float*)d_in[6];
    const float* W_vn   = (const float*)d_in[7];
    const float* W_brms = (const float*)d_in[8];
    const float* W_bproj= (const float*)d_in[9];
    const float* W_out  = (const float*)d_in[10];
    const float* W_ffpre = (const float*)d_in[11];
    const float* W_ffpost= (const float*)d_in[12];
    const float* W_ff1  = (const float*)d_in[13];
    const float* B_ff1  = (const float*)d_in[14];
    const float* W_ff2  = (const float*)d_in[15];
    const float* B_ff2  = (const float*)d_in[16];
    const float* W_ppre = (const float*)d_in[17];
    const float* W_pqk  = (const float*)d_in[18];
    const float* W_pv   = (const float*)d_in[19];
    const float* B_pv   = (const float*)d_in[20];
    const float* W_pffpre = (const float*)d_in[21];
    const float* W_pff1 = (const float*)d_in[22];
    const float* B_pff1 = (const float*)d_in[23];
    const float* W_pff2 = (const float*)d_in[24];
    const float* B_pff2 = (const float*)d_in[25];

    float *xn, *qkv, *q, *k, *v, *pb, *ao, *t1;
    float *pxn, *pqk, *pv, *psim, *pt, *pt2;
    cudaGetSymbolAddress((void**)&xn, g_xn);
    cudaGetSymbolAddress((void**)&qkv, g_qkv);
    cudaGetSymbolAddress((void**)&q, g_q);
    cudaGetSymbolAddress((void**)&k, g_k);
    cudaGetSymbolAddress((void**)&v, g_v);
    cudaGetSymbolAddress((void**)&pb, g_pb);
    cudaGetSymbolAddress((void**)&ao, g_ao);
    cudaGetSymbolAddress((void**)&t1, g_t1);
    cudaGetSymbolAddress((void**)&pxn, g_pxn);
    cudaGetSymbolAddress((void**)&pqk, g_pqk);
    cudaGetSymbolAddress((void**)&pv, g_pv);
    cudaGetSymbolAddress((void**)&psim, g_psim);
    cudaGetSymbolAddress((void**)&pt, g_pt);
    cudaGetSymbolAddress((void**)&pt2, g_pt2);

    /* residual streams live directly in d_out: [single | pairwise] */
    float* single = (float*)d_out;
    float* pair   = (float*)d_out + (size_t)SEQn * Dn;
    cudaMemcpyAsync(single, in_single, (size_t)SEQn * Dn * 4, cudaMemcpyDeviceToDevice);
    cudaMemcpyAsync(pair, in_pair, (size_t)NPn * NPn * DPn * 4, cudaMemcpyDeviceToDevice);

    cudaFuncSetAttribute(flash_attn_k, cudaFuncAttributeMaxDynamicSharedMemorySize,
                         FA_SMEM * 4);

    for (int i = 0; i < 4; i++) {
        /* ---- single-track attention ---- */
        rmsnorm_k<<<SEQn, 256>>>(single, W_attn_pre + i * Dn, xn, Dn);
        launch_gemm(false, SEQn, NQKVn, Dn, xn, Dn, 0,
                    W_qkv + (long long)i * Dn * NQKVn, NQKVn, 0, qkv, NQKVn, 0, 1, nullptr, 0);
        qkv_post_k<<<dim3(SEQn, 10), 192>>>(qkv, W_qn + i * DQKn, W_kn + i * DQKn,
                                            W_vn + i * DVn, q, k, v);
        pb_kernel<<<NPn * NPn, 128>>>(pair, W_brms + i * DPn, W_bproj + i * DPn * Hn, pb);
        flash_attn_k<<<dim3(SEQn / 64, Hn), 256, FA_SMEM * 4>>>(q, k, v, pb, ao);
        launch_gemm(false, SEQn, Dn, Hn * DVn, ao, Hn * DVn, 0,
                    W_out + (long long)i * Hn * DVn * Dn, Dn, 0, t1, Dn, 0, 1, nullptr, 0);
        rmsnorm_add_k<<<SEQn, 256>>>(t1, W_attn_post + i * Dn, single, Dn);

        /* ---- single-track FF ---- */
        rmsnorm_k<<<SEQn, 256>>>(single, W_ffpre + i * Dn, xn, Dn);
        launch_gemm(false, SEQn, FFIn, Dn, xn, Dn, 0,
                    W_ff1 + (long long)i * Dn * FFIn, FFIn, 0, ao, FFIn, 0, 1,
                    B_ff1 + i * FFIn, 1);
        launch_gemm(false, SEQn, Dn, FFIn, ao, FFIn, 0,
                    W_ff2 + (long long)i * FFIn * Dn, Dn, 0, t1, Dn, 0, 1,
                    B_ff2 + i * Dn, 0);
        rmsnorm_add_k<<<SEQn, 256>>>(t1, W_ffpost + i * Dn, single, Dn);

        /* ---- pairwise track (layers 0, 2) ---- */
        if ((i & 1) == 0) {
            int j = i / 2;
            rmsnorm_k<<<NPn * NPn, 128>>>(pair, W_ppre + j * DPn, pxn, DPn);
            launch_gemm(false, NPn * NPn, 2 * DPn, DPn, pxn, DPn, 0,
                        W_pqk + (long long)j * DPn * 2 * DPn, 2 * DPn, 0,
                        pqk, 2 * DPn, 0, 1, nullptr, 0);
            launch_gemm(false, NPn * NPn, DPn, DPn, pxn, DPn, 0,
                        W_pv + (long long)j * DPn * DPn, DPn, 0,
                        pv, DPn, 0, 1, B_pv + j * DPn, 0);
            launch_gemm(true, NPn, NPn, DPn, pqk, 2 * DPn, (long long)NPn * 2 * DPn,
                        pqk + DPn, 2 * DPn, (long long)NPn * 2 * DPn,
                        psim, NPn, (long long)NPn * NPn, NPn, nullptr, 0);
            softmax_p_k<<<NPn * NPn, NPn>>>(psim);
            launch_gemm(false, NPn, DPn, NPn, psim, NPn, (long long)NPn * NPn,
                        pv, DPn, (long long)NPn * DPn,
                        pt2, DPn, (long long)NPn * DPn, NPn, nullptr, 0);
            add_k<<<(NPn * NPn * DPn + 255) / 256, 256>>>(pair, pt2, (long long)NPn * NPn * DPn);
            rmsnorm_k<<<NPn * NPn, 128>>>(pair, W_pffpre + j * DPn, pxn, DPn);
            launch_gemm(false, NPn * NPn, DPIn, DPn, pxn, DPn, 0,
                        W_pff1 + (long long)j * DPn * DPIn, DPIn, 0,
                        pt, DPIn, 0, 1, B_pff1 + j * DPIn, 1);
            launch_gemm(false, NPn * NPn, DPn, DPIn, pt, DPIn, 0,
                        W_pff2 + (long long)j * DPIn * DPn, DPn, 0,
                        pt2, DPn, 0, 1, B_pff2 + j * DPn, 0);
            add_k<<<(NPn * NPn * DPn + 255) / 256, 256>>>(pair, pt2, (long long)NPn * NPn * DPn);
        }
    }
}

// round 5
// speedup vs baseline: 1.1212x; 1.1212x over previous
#include <cuda_runtime.h>
#include <math.h>

#define SEQn 2048
#define Dn   768
#define Hn   8
#define DQKn 128
#define DVn  192
#define NQKVn 1344   /* 8*128 + 128 + 192 */
#define NPn  256
#define DPn  128
#define FFIn 1536
#define DPIn 256
#define EPS_RMS 1.1920929e-07f
#define EPS_LN  1e-5f

/* ---------------- scratch (device globals; no allocation) ---------------- */
__device__ float g_xn[SEQn * Dn];
__device__ float g_qkv[SEQn * NQKVn];
__device__ float g_q[Hn * SEQn * DQKn];
__device__ float g_k[SEQn * DQKn];
__device__ float g_v[SEQn * DVn];
__device__ float g_sim[(size_t)Hn * SEQn * SEQn];      /* 134 MB */
__device__ float g_pb[Hn * NPn * NPn];
__device__ float g_ao[SEQn * Hn * DVn];
__device__ float g_t1[SEQn * FFIn];
__device__ float g_rsum[Hn * SEQn];
__device__ float g_pxn[NPn * NPn * DPn];
__device__ float g_pqk[NPn * NPn * 2 * DPn];
__device__ float g_pv[NPn * NPn * DPn];
__device__ float g_psim[(size_t)NPn * NPn * NPn];      /* 67 MB */
__device__ float g_prsum[NPn * NPn];
__device__ float g_pt[NPn * NPn * DPIn];

/* ---------------- reductions ---------------- */
template <int OP>
__device__ __forceinline__ float blockReduce(float v) {
    __shared__ float s[33];
    int lane = threadIdx.x & 31, wid = threadIdx.x >> 5;
#pragma unroll
    for (int o = 16; o > 0; o >>= 1) {
        float ov = __shfl_down_sync(0xffffffffu, v, o);
        v = (OP == 0) ? (v + ov) : fmaxf(v, ov);
    }
    if (lane == 0) s[wid] = v;
    __syncthreads();
    if (threadIdx.x == 0) {
        int nw = (blockDim.x + 31) >> 5;
        float r = s[0];
        for (int i = 1; i < nw; i++) r = (OP == 0) ? (r + s[i]) : fmaxf(r, s[i]);
        s[32] = r;
    }
    __syncthreads();
    float r = s[32];
    __syncthreads();
    return r;
}

__global__ void zero_k(float* p, int n)
{
    int i = blockIdx.x * blockDim.x + threadIdx.x;
    if (i < n) p[i] = 0.f;
}

/* ---------------- 128x128x8 double-buffered SGEMM with fused epilogues ----
   MODE: 0 plain(+bias), 1 relu(+bias), 2 accumulate into C(+bias),
         3 sim softmax: exp(softclamp(x+pb)) + atomic row sums,
         4 pair softmax: exp(x) + atomic row sums.
   rscale (optional): multiply output rows by 1/rscale[batch*M+m].
   Requires M % 128 == 0, K % 8 == 0 (N guarded).                            */
template <bool TB, int MODE>
__global__ __launch_bounds__(256) void gemm128_kernel(
    int M, int N, int K,
    const float* __restrict__ A, int lda, long long sA,
    const float* __restrict__ B, int ldb, long long sB,
    float* __restrict__ C, int ldc, long long sC,
    const float* __restrict__ bias,
    const float* __restrict__ pbias,
    float* __restrict__ rsum,
    const float* __restrict__ rscale)
{
    __shared__ float As[2][8][128];
    __shared__ float Bs[2][8][128];
    const int batch = blockIdx.z;
    A += (long long)batch * sA;
    B += (long long)batch * sB;
    C += (long long)batch * sC;
    const int bm = blockIdx.y * 128, bn = blockIdx.x * 128;
    const int tid = threadIdx.x;
    const int tx = tid & 15, ty = tid >> 4;

    const int arow = tid >> 1, akq = (tid & 1) * 4;
    const float* Aptr = A + (long long)(bm + arow) * lda + akq;

    const int brow = tid >> 1, bkq = (tid & 1) * 4;
    const int bkr = tid >> 5, bnq = (tid & 31) * 4;
    const bool bvalid = TB ? (bn + brow < N) : (bn + bnq < N);
    const float4 f0 = make_float4(0.f, 0.f, 0.f, 0.f);

    float4 aReg, bReg;
    aReg = *(const float4*)(Aptr);
    if (TB)  bReg = bvalid ? *(const float4*)(B + (long long)(bn + brow) * ldb + bkq) : f0;
    else     bReg = bvalid ? *(const float4*)(B + (long long)bkr * ldb + bn + bnq)    : f0;

    As[0][akq + 0][arow] = aReg.x;
    As[0][akq + 1][arow] = aReg.y;
    As[0][akq + 2][arow] = aReg.z;
    As[0][akq + 3][arow] = aReg.w;
    if (TB) {
        Bs[0][bkq + 0][brow] = bReg.x;
        Bs[0][bkq + 1][brow] = bReg.y;
        Bs[0][bkq + 2][brow] = bReg.z;
        Bs[0][bkq + 3][brow] = bReg.w;
    } else {
        *(float4*)&Bs[0][bkr][bnq] = bReg;
    }
    __syncthreads();

    float acc[8][8];
#pragma unroll
    for (int i = 0; i < 8; i++)
#pragma unroll
        for (int j = 0; j < 8; j++) acc[i][j] = 0.f;

    const int nt = K >> 3;
    int buf = 0;
    for (int kt = 0; kt < nt; kt++) {
        if (kt + 1 < nt) {
            int k0 = (kt + 1) << 3;
            aReg = *(const float4*)(Aptr + k0);
            if (TB)  bReg = bvalid ? *(const float4*)(B + (long long)(bn + brow) * ldb + k0 + bkq) : f0;
            else     bReg = bvalid ? *(const float4*)(B + (long long)(k0 + bkr) * ldb + bn + bnq)  : f0;
        }
#pragma unroll
        for (int kk = 0; kk < 8; kk++) {
            float a[8], b[8];
            *(float4*)&a[0] = *(const float4*)&As[buf][kk][ty * 4];
            *(float4*)&a[4] = *(const float4*)&As[buf][kk][64 + ty * 4];
            *(float4*)&b[0] = *(const float4*)&Bs[buf][kk][tx * 4];
            *(float4*)&b[4] = *(const float4*)&Bs[buf][kk][64 + tx * 4];
#pragma unroll
            for (int i = 0; i < 8; i++)
#pragma unroll
                for (int j = 0; j < 8; j++) acc[i][j] = fmaf(a[i], b[j], acc[i][j]);
        }
        if (kt + 1 < nt) {
            buf ^= 1;
            As[buf][akq + 0][arow] = aReg.x;
            As[buf][akq + 1][arow] = aReg.y;
            As[buf][akq + 2][arow] = aReg.z;
            As[buf][akq + 3][arow] = aReg.w;
            if (TB) {
                Bs[buf][bkq + 0][brow] = bReg.x;
                Bs[buf][bkq + 1][brow] = bReg.y;
                Bs[buf][bkq + 2][brow] = bReg.z;
                Bs[buf][bkq + 3][brow] = bReg.w;
            } else {
                *(float4*)&Bs[buf][bkr][bnq] = bReg;
            }
        }
        __syncthreads();
    }

#pragma unroll
    for (int ih = 0; ih < 2; ih++) {
#pragma unroll
        for (int ii = 0; ii < 4; ii++) {
            const int m = bm + ih * 64 + ty * 4 + ii;
            float inv = 1.f;
            if (rscale) inv = 1.f / rscale[(size_t)batch * M + m];
            const float* pbr = (MODE == 3)
                ? pbias + (size_t)batch * (NPn * NPn) + (size_t)(m >> 3) * NPn : nullptr;
            float rowacc = 0.f;
#pragma unroll
            for (int jh = 0; jh < 2; jh++) {
                int n = bn + jh * 64 + tx * 4;
                if (n < N) {
                    float v[4];
                    v[0] = acc[ih * 4 + ii][jh * 4 + 0];
                    v[1] = acc[ih * 4 + ii][jh * 4 + 1];
                    v[2] = acc[ih * 4 + ii][jh * 4 + 2];
                    v[3] = acc[ih * 4 + ii][jh * 4 + 3];
                    if (bias) {
                        v[0] += bias[n + 0]; v[1] += bias[n + 1];
                        v[2] += bias[n + 2]; v[3] += bias[n + 3];
                    }
                    if (MODE == 1) {
#pragma unroll
                        for (int j = 0; j < 4; j++) v[j] = fmaxf(v[j], 0.f);
                    }
                    if (MODE == 3) {
#pragma unroll
                        for (int j = 0; j < 4; j++) {
                            float x = v[j] + pbr[(n + j) >> 3];
                            float t = __expf(-0.4f * fabsf(x));
                            float th = __fdividef(1.f - t, 1.f + t);
                            float p = __expf(copysignf(5.f * th, x));
                            rowacc += p;
                            v[j] = p;
                        }
                    }
                    if (MODE == 4) {
#pragma unroll
                        for (int j = 0; j < 4; j++) {
                            float p = __expf(v[j]);
                            rowacc += p;
                            v[j] = p;
                        }
                    }
                    if (rscale) {
#pragma unroll
                        for (int j = 0; j < 4; j++) v[j] *= inv;
                    }
                    float4 w;
                    if (MODE == 2) {
                        float4 old = *(const float4*)&C[(long long)m * ldc + n];
                        w.x = v[0] + old.x; w.y = v[1] + old.y;
                        w.z = v[2] + old.z; w.w = v[3] + old.w;
                    } else {
                        w.x = v[0]; w.y = v[1]; w.z = v[2]; w.w = v[3];
                    }
                    *(float4*)&C[(long long)m * ldc + n] = w;
                }
            }
            if (MODE == 3 || MODE == 4) {
#pragma unroll
                for (int off = 8; off > 0; off >>= 1)
                    rowacc += __shfl_xor_sync(0xffffffffu, rowacc, off);
                if (tx == 0) atomicAdd(&rsum[(size_t)batch * M + m], rowacc);
            }
        }
    }
}

/* ---------------- norms ---------------- */
__global__ void rmsnorm_k(const float* __restrict__ x, const float* __restrict__ w,
                          float* __restrict__ y, int cols)
{
    long long r = blockIdx.x;
    const float* xr = x + r * cols;
    float ss = 0.f;
    for (int c = threadIdx.x; c < cols; c += blockDim.x) { float v = xr[c]; ss += v * v; }
    ss = blockReduce<0>(ss);
    float inv = rsqrtf(ss / cols + EPS_RMS);
    for (int c = threadIdx.x; c < cols; c += blockDim.x)
        y[r * cols + c] = xr[c] * inv * w[c];
}

/* res += rmsnorm(x)*w1; if (w2) out = rmsnorm(res)*w2.  cols=768, 256 thr. */
__global__ void rmsnorm_add_norm_k(const float* __restrict__ x, const float* __restrict__ w1,
                                   float* __restrict__ res, const float* __restrict__ w2,
                                   float* __restrict__ out)
{
    long long r = blockIdx.x;
    const int cols = Dn;
    const float* xr = x + r * cols;
    float xv[3], rv[3];
    float ss = 0.f;
#pragma unroll
    for (int u = 0; u < 3; u++) {
        xv[u] = xr[threadIdx.x + u * 256];
        ss += xv[u] * xv[u];
    }
    ss = blockReduce<0>(ss);
    float inv = rsqrtf(ss / cols + EPS_RMS);
    float ss2 = 0.f;
#pragma unroll
    for (int u = 0; u < 3; u++) {
        int c = threadIdx.x + u * 256;
        float v = res[r * cols + c] + xv[u] * inv * w1[c];
        res[r * cols + c] = v;
        rv[u] = v;
        ss2 += v * v;
    }
    if (w2) {
        ss2 = blockReduce<0>(ss2);
        float inv2 = rsqrtf(ss2 / cols + EPS_RMS);
#pragma unroll
        for (int u = 0; u < 3; u++) {
            int c = threadIdx.x + u * 256;
            out[r * cols + c] = rv[u] * inv2 * w2[c];
        }
    }
}

/* ---------------- qkv post: per-head LayerNorm + scale + rotary ---------------- */
__global__ void qkv_post_k(const float* __restrict__ qkv,
                           const float* __restrict__ qn, const float* __restrict__ kn,
                           const float* __restrict__ vn,
                           float* __restrict__ q, float* __restrict__ k, float* __restrict__ v)
{
    int n = blockIdx.x, s = blockIdx.y, t = threadIdx.x;
    int len = (s == 9) ? 192 : 128;
    int off = (s < 8) ? s * 128 : (s == 8 ? 1024 : 1152);
    __shared__ float xs[192];
    float x = 0.f;
    if (t < len) x = qkv[(long long)n * NQKVn + off + t];
    float sum = blockReduce<0>(t < len ? x : 0.f);
    float sq  = blockReduce<0>(t < len ? x * x : 0.f);
    float mu = sum / len;
    float var = sq / len - mu * mu;
    float inv = rsqrtf(var + EPS_LN);
    float y = 0.f;
    if (t < len) {
        const float* w = (s < 8) ? qn : (s == 8 ? kn : vn);
        y = (x - mu) * inv * w[t];
        if (s < 8) y *= 0.125f;
    }
    if (s == 9) { if (t < 192) v[n * DVn + t] = y; return; }
    xs[t] = y;
    __syncthreads();
    if (t < 128) {
        int d2 = t & 63;
        float invf = (d2 == 0) ? 0.1f : 0.0f;
        float f = (float)n * invf;
        float c = cosf(f), si = sinf(f);
        float rh = (t < 64) ? -xs[t + 64] : xs[t - 64];
        float out = y * c + rh * si;
        if (s < 8) q[((size_t)s * SEQn + n) * DQKn + t] = out;
        else       k[n * DQKn + t] = out;
    }
}

/* ------------- pairwise bias: rms -> gelu -> [128->8], warp per (i,j) ------------- */
__global__ __launch_bounds__(256) void pb_kernel(
    const float* __restrict__ pair, const float* __restrict__ rw,
    const float* __restrict__ proj, float* __restrict__ pb)
{
    int warp = (blockIdx.x * blockDim.x + threadIdx.x) >> 5;   /* 0..65535 */
    int lane = threadIdx.x & 31;
    float4 x = *(const float4*)(pair + (size_t)warp * DPn + lane * 4);
    float ss = x.x * x.x + x.y * x.y + x.z * x.z + x.w * x.w;
#pragma unroll
    for (int off = 16; off > 0; off >>= 1)
        ss += __shfl_xor_sync(0xffffffffu, ss, off);
    float inv = rsqrtf(ss * (1.f / DPn) + EPS_RMS);
    float4 w4 = *(const float4*)(rw + lane * 4);
    float g[4];
    {
        float y0 = x.x * inv * w4.x, y1 = x.y * inv * w4.y;
        float y2 = x.z * inv * w4.z, y3 = x.w * inv * w4.w;
        g[0] = 0.5f * y0 * (1.f + erff(y0 * 0.70710678118654752f));
        g[1] = 0.5f * y1 * (1.f + erff(y1 * 0.70710678118654752f));
        g[2] = 0.5f * y2 * (1.f + erff(y2 * 0.70710678118654752f));
        g[3] = 0.5f * y3 * (1.f + erff(y3 * 0.70710678118654752f));
    }
    float p[8] = {0.f, 0.f, 0.f, 0.f, 0.f, 0.f, 0.f, 0.f};
#pragma unroll
    for (int c = 0; c < 4; c++) {
        const float* pr = proj + (size_t)(lane * 4 + c) * Hn;
        float4 a = *(const float4*)pr;
        float4 b = *(const float4*)(pr + 4);
        p[0] = fmaf(g[c], a.x, p[0]); p[1] = fmaf(g[c], a.y, p[1]);
        p[2] = fmaf(g[c], a.z, p[2]); p[3] = fmaf(g[c], a.w, p[3]);
        p[4] = fmaf(g[c], b.x, p[4]); p[5] = fmaf(g[c], b.y, p[5]);
        p[6] = fmaf(g[c], b.z, p[6]); p[7] = fmaf(g[c], b.w, p[7]);
    }
#pragma unroll
    for (int off = 16; off > 0; off >>= 1)
#pragma unroll
        for (int h = 0; h < 8; h++)
            p[h] += __shfl_xor_sync(0xffffffffu, p[h], off);
    if (lane < 8) {
        int i = warp >> 8, j = warp & 255;
        pb[((size_t)lane * NPn + i) * NPn + j] = p[lane];
    }
}

/* ---------------- host launcher ---------------- */
static inline void launch_gemm(bool tb, int mode, int M, int N, int K,
                               const float* A, int lda, long long sA,
                               const float* B, int ldb, long long sB,
                               float* C, int ldc, long long sC, int batch,
                               const float* bias, const float* pbias,
                               float* rsum, const float* rscale)
{
    dim3 g((N + 127) / 128, M / 128, batch), b(256);
    if (tb) {
        if (mode == 3) gemm128_kernel<true, 3><<<g, b>>>(M, N, K, A, lda, sA, B, ldb, sB, C, ldc, sC, bias, pbias, rsum, rscale);
        else if (mode == 4) gemm128_kernel<true, 4><<<g, b>>>(M, N, K, A, lda, sA, B, ldb, sB, C, ldc, sC, bias, pbias, rsum, rscale);
        else gemm128_kernel<true, 0><<<g, b>>>(M, N, K, A, lda, sA, B, ldb, sB, C, ldc, sC, bias, pbias, rsum, rscale);
    } else {
        if (mode == 1) gemm128_kernel<false, 1><<<g, b>>>(M, N, K, A, lda, sA, B, ldb, sB, C, ldc, sC, bias, pbias, rsum, rscale);
        else if (mode == 2) gemm128_kernel<false, 2><<<g, b>>>(M, N, K, A, lda, sA, B, ldb, sB, C, ldc, sC, bias, pbias, rsum, rscale);
        else gemm128_kernel<false, 0><<<g, b>>>(M, N, K, A, lda, sA, B, ldb, sB, C, ldc, sC, bias, pbias, rsum, rscale);
    }
}

extern "C" void kernel_launch(void* const* d_in, const int* in_sizes, int n_in,
                              void* d_out, int out_size)
{
    (void)in_sizes; (void)n_in; (void)out_size;
    const float* in_single = (const float*)d_in[0];
    const float* in_pair   = (const float*)d_in[1];
    const float* W_attn_pre  = (const float*)d_in[2];
    const float* W_attn_post = (const float*)d_in[3];
    const float* W_qkv  = (const float*)d_in[4];
    const float* W_qn   = (const float*)d_in[5];
    const float* W_kn   = (const float*)d_in[6];
    const float* W_vn   = (const float*)d_in[7];
    const float* W_brms = (const float*)d_in[8];
    const float* W_bproj= (const float*)d_in[9];
    const float* W_out  = (const float*)d_in[10];
    const float* W_ffpre = (const float*)d_in[11];
    const float* W_ffpost= (const float*)d_in[12];
    const float* W_ff1  = (const float*)d_in[13];
    const float* B_ff1  = (const float*)d_in[14];
    const float* W_ff2  = (const float*)d_in[15];
    const float* B_ff2  = (const float*)d_in[16];
    const float* W_ppre = (const float*)d_in[17];
    const float* W_pqk  = (const float*)d_in[18];
    const float* W_pv   = (const float*)d_in[19];
    const float* B_pv   = (const float*)d_in[20];
    const float* W_pffpre = (const float*)d_in[21];
    const float* W_pff1 = (const float*)d_in[22];
    const float* B_pff1 = (const float*)d_in[23];
    const float* W_pff2 = (const float*)d_in[24];
    const float* B_pff2 = (const float*)d_in[25];

    float *xn, *qkv, *q, *k, *v, *sim, *pb, *ao, *t1, *rsum;
    float *pxn, *pqk, *pv, *psim, *prsum, *pt;
    cudaGetSymbolAddress((void**)&xn, g_xn);
    cudaGetSymbolAddress((void**)&qkv, g_qkv);
    cudaGetSymbolAddress((void**)&q, g_q);
    cudaGetSymbolAddress((void**)&k, g_k);
    cudaGetSymbolAddress((void**)&v, g_v);
    cudaGetSymbolAddress((void**)&sim, g_sim);
    cudaGetSymbolAddress((void**)&pb, g_pb);
    cudaGetSymbolAddress((void**)&ao, g_ao);
    cudaGetSymbolAddress((void**)&t1, g_t1);
    cudaGetSymbolAddress((void**)&rsum, g_rsum);
    cudaGetSymbolAddress((void**)&pxn, g_pxn);
    cudaGetSymbolAddress((void**)&pqk, g_pqk);
    cudaGetSymbolAddress((void**)&pv, g_pv);
    cudaGetSymbolAddress((void**)&psim, g_psim);
    cudaGetSymbolAddress((void**)&prsum, g_prsum);
    cudaGetSymbolAddress((void**)&pt, g_pt);

    /* residual streams live directly in d_out: [single | pairwise] */
    float* single = (float*)d_out;
    float* pair   = (float*)d_out + (size_t)SEQn * Dn;
    cudaMemcpyAsync(single, in_single, (size_t)SEQn * Dn * 4, cudaMemcpyDeviceToDevice);
    cudaMemcpyAsync(pair, in_pair, (size_t)NPn * NPn * DPn * 4, cudaMemcpyDeviceToDevice);

    /* xn = rmsnorm(single, attn_pre[0]) for the first layer */
    rmsnorm_k<<<SEQn, 256>>>(single, W_attn_pre, xn, Dn);

    for (int i = 0; i < 4; i++) {
        /* ---- single-track attention ---- */
        launch_gemm(false, 0, SEQn, NQKVn, Dn, xn, Dn, 0,
                    W_qkv + (long long)i * Dn * NQKVn, NQKVn, 0, qkv, NQKVn, 0, 1,
                    nullptr, nullptr, nullptr, nullptr);
        qkv_post_k<<<dim3(SEQn, 10), 192>>>(qkv, W_qn + i * DQKn, W_kn + i * DQKn,
                                            W_vn + i * DVn, q, k, v);
        pb_kernel<<<NPn * NPn / 8, 256>>>(pair, W_brms + i * DPn, W_bproj + i * DPn * Hn, pb);
        zero_k<<<(Hn * SEQn + 255) / 256, 256>>>(rsum, Hn * SEQn);
        /* P = exp(softclamp(qk^T + pb)), rowsums accumulated */
        launch_gemm(true, 3, SEQn, SEQn, DQKn, q, DQKn, (long long)SEQn * DQKn,
                    k, DQKn, 0, sim, SEQn, (long long)SEQn * SEQn, Hn,
                    nullptr, pb, rsum, nullptr);
        /* O = (P/rowsum) V */
        launch_gemm(false, 0, SEQn, DVn, SEQn, sim, SEQn, (long long)SEQn * SEQn,
                    v, DVn, 0, ao, Hn * DVn, DVn, Hn,
                    nullptr, nullptr, nullptr, rsum);
        launch_gemm(false, 0, SEQn, Dn, Hn * DVn, ao, Hn * DVn, 0,
                    W_out + (long long)i * Hn * DVn * Dn, Dn, 0, t1, Dn, 0, 1,
                    nullptr, nullptr, nullptr, nullptr);
        /* single += rms(t1)*attn_post; xn = rms(single)*ff_pre */
        rmsnorm_add_norm_k<<<SEQn, 256>>>(t1, W_attn_post + i * Dn, single,
                                          W_ffpre + i * Dn, xn);

        /* ---- single-track FF ---- */
        launch_gemm(false, 1, SEQn, FFIn, Dn, xn, Dn, 0,
                    W_ff1 + (long long)i * Dn * FFIn, FFIn, 0, ao, FFIn, 0, 1,
                    B_ff1 + i * FFIn, nullptr, nullptr, nullptr);
        launch_gemm(false, 0, SEQn, Dn, FFIn, ao, FFIn, 0,
                    W_ff2 + (long long)i * FFIn * Dn, Dn, 0, t1, Dn, 0, 1,
                    B_ff2 + i * Dn, nullptr, nullptr, nullptr);
        /* single += rms(t1)*ff_post; xn = rms(single)*attn_pre[i+1] (if any) */
        rmsnorm_add_norm_k<<<SEQn, 256>>>(t1, W_ffpost + i * Dn, single,
                                          (i < 3) ? W_attn_pre + (i + 1) * Dn : nullptr, xn);

        /* ---- pairwise track (layers 0, 2) ---- */
        if ((i & 1) == 0) {
            int j = i / 2;
            rmsnorm_k<<<NPn * NPn, 128>>>(pair, W_ppre + j * DPn, pxn, DPn);
            launch_gemm(false, 0, NPn * NPn, 2 * DPn, DPn, pxn, DPn, 0,
                        W_pqk + (long long)j * DPn * 2 * DPn, 2 * DPn, 0,
                        pqk, 2 * DPn, 0, 1, nullptr, nullptr, nullptr, nullptr);
            launch_gemm(false, 0, NPn * NPn, DPn, DPn, pxn, DPn, 0,
                        W_pv + (long long)j * DPn * DPn, DPn, 0,
                        pv, DPn, 0, 1, B_pv + j * DPn, nullptr, nullptr, nullptr);
            zero_k<<<(NPn * NPn + 255) / 256, 256>>>(prsum, NPn * NPn);
            launch_gemm(true, 4, NPn, NPn, DPn, pqk, 2 * DPn, (long long)NPn * 2 * DPn,
                        pqk + DPn, 2 * DPn, (long long)NPn * 2 * DPn,
                        psim, NPn, (long long)NPn * NPn, NPn,
                        nullptr, nullptr, prsum, nullptr);
            /* pair += (P/rowsum) V */
            launch_gemm(false, 2, NPn, DPn, NPn, psim, NPn, (long long)NPn * NPn,
                        pv, DPn, (long long)NPn * DPn,
                        pair, DPn, (long long)NPn * DPn, NPn,
                        nullptr, nullptr, nullptr, prsum);
            rmsnorm_k<<<NPn * NPn, 128>>>(pair, W_pffpre + j * DPn, pxn, DPn);
            launch_gemm(false, 1, NPn * NPn, DPIn, DPn, pxn, DPn, 0,
                        W_pff1 + (long long)j * DPn * DPIn, DPIn, 0,
                        pt, DPIn, 0, 1, B_pff1 + j * DPIn, nullptr, nullptr, nullptr);
            /* pair += ff2(pt) */
            launch_gemm(false, 2, NPn * NPn, DPn, DPIn, pt, DPIn, 0,
                        W_pff2 + (long long)j * DPIn * DPn, DPn, 0,
                        pair, DPn, 0, 1, B_pff2 + j * DPn, nullptr, nullptr, nullptr);
        }
    }
}

// round 6
// speedup vs baseline: 2.3246x; 2.0733x over previous
#include <cuda_runtime.h>
#include <math.h>

#define SEQn 2048
#define Dn   768
#define Hn   8
#define DQKn 128
#define DVn  192
#define NQKVn 1344   /* 8*128 + 128 + 192 */
#define NPn  256
#define DPn  128
#define FFIn 1536
#define DPIn 256
#define EPS_RMS 1.1920929e-07f
#define EPS_LN  1e-5f

/* ---------------- scratch (device globals; no allocation) ---------------- */
__device__ float g_xn[SEQn * Dn];
__device__ float g_qkv[SEQn * NQKVn];
__device__ float g_q[Hn * SEQn * DQKn];
__device__ float g_k[SEQn * DQKn];
__device__ float g_v[SEQn * DVn];
__device__ float g_sim[(size_t)Hn * SEQn * SEQn];      /* 134 MB */
__device__ float g_pb[Hn * NPn * NPn];
__device__ float g_ao[SEQn * Hn * DVn];
__device__ float g_t1[SEQn * FFIn];
__device__ float g_rsum[Hn * SEQn];
__device__ float g_pxn[NPn * NPn * DPn];
__device__ float g_pqk[NPn * NPn * 2 * DPn];
__device__ float g_pv[NPn * NPn * DPn];
__device__ float g_psim[(size_t)NPn * NPn * NPn];      /* 67 MB */
__device__ float g_prsum[NPn * NPn];
__device__ float g_pt[NPn * NPn * DPIn];

/* ---------------- helpers ---------------- */
__device__ __forceinline__ unsigned f2tf32(float x) {
    unsigned r;
    asm("cvt.rna.tf32.f32 %0, %1;" : "=r"(r) : "f"(x));
    return r;
}

__device__ __forceinline__ void mma_tf32(float* c, const unsigned* a, const unsigned* b) {
    asm volatile(
        "mma.sync.aligned.m16n8k8.row.col.f32.tf32.tf32.f32 "
        "{%0,%1,%2,%3}, {%4,%5,%6,%7}, {%8,%9}, {%0,%1,%2,%3};\n"
        : "+f"(c[0]), "+f"(c[1]), "+f"(c[2]), "+f"(c[3])
        : "r"(a[0]), "r"(a[1]), "r"(a[2]), "r"(a[3]), "r"(b[0]), "r"(b[1]));
}

__device__ __forceinline__ float softclamp_exp(float x) {
    float t = __expf(-0.4f * fabsf(x));
    float th = __fdividef(1.f - t, 1.f + t);
    return __expf(copysignf(5.f * th, x));
}

template <int OP>
__device__ __forceinline__ float blockReduce(float v) {
    __shared__ float s[33];
    int lane = threadIdx.x & 31, wid = threadIdx.x >> 5;
#pragma unroll
    for (int o = 16; o > 0; o >>= 1) {
        float ov = __shfl_down_sync(0xffffffffu, v, o);
        v = (OP == 0) ? (v + ov) : fmaxf(v, ov);
    }
    if (lane == 0) s[wid] = v;
    __syncthreads();
    if (threadIdx.x == 0) {
        int nw = (blockDim.x + 31) >> 5;
        float r = s[0];
        for (int i = 1; i < nw; i++) r = (OP == 0) ? (r + s[i]) : fmaxf(r, s[i]);
        s[32] = r;
    }
    __syncthreads();
    float r = s[32];
    __syncthreads();
    return r;
}

__global__ void zero_k(float* p, int n)
{
    int i = blockIdx.x * blockDim.x + threadIdx.x;
    if (i < n) p[i] = 0.f;
}

/* ---------------- TF32 tensor-core GEMM, 128x128 CTA, BK=16, dbl-buffered.
   MODE: 0 plain(+bias), 1 relu(+bias), 2 accumulate into C(+bias),
         3 sim softmax: exp(softclamp(x+pb)) + atomic row sums,
         4 pair softmax: exp(x) + atomic row sums.
   rscale (optional): multiply output rows by 1/rscale[batch*M+m].
   Requires M % 128 == 0, K % 16 == 0 (N guarded).                         */
template <bool TB, int MODE>
__global__ __launch_bounds__(256) void gemm_tc(
    int M, int N, int K,
    const float* __restrict__ A, int lda, long long sA,
    const float* __restrict__ B, int ldb, long long sB,
    float* __restrict__ C, int ldc, long long sC,
    const float* __restrict__ bias,
    const float* __restrict__ pbias,
    float* __restrict__ rsum,
    const float* __restrict__ rscale)
{
    __shared__ unsigned As[2][16][136];   /* stride 136 ≡ 8 mod 32: frag loads conflict-free */
    __shared__ unsigned Bs[2][16][136];
    const int batch = blockIdx.z;
    A += (long long)batch * sA;
    B += (long long)batch * sB;
    C += (long long)batch * sC;
    const int bm = blockIdx.y * 128, bn = blockIdx.x * 128;
    const int tid = threadIdx.x;
    const int lane = tid & 31, warp = tid >> 5;
    const int g = lane >> 2, tg = lane & 3;
    const int warpM = warp & 1, warpN = warp >> 1;   /* 2 x 4 warps -> 64 x 32 tiles */

    /* staging maps */
    const int arow = tid >> 1, ak8 = (tid & 1) * 8;          /* A: 128 rows x 16 k */
    const float* Aptr = A + (long long)(bm + arow) * lda + ak8;
    const int brow = tid >> 1, bk8 = (tid & 1) * 8;          /* TB:  n-row, k segment */
    const int bkr = tid >> 4, bn8 = (tid & 15) * 8;          /* !TB: k-row, n segment */
    const bool bval_t  = TB ? (bn + brow < N) : true;
    const bool bval_n0 = TB ? true : (bn + bn8 < N);
    const bool bval_n1 = TB ? true : (bn + bn8 + 4 < N);
    const float4 f0 = make_float4(0.f, 0.f, 0.f, 0.f);

    float4 pa0, pa1, pb0, pb1;
    /* prefetch stage 0 */
    {
        pa0 = *(const float4*)(Aptr);
        pa1 = *(const float4*)(Aptr + 4);
        if (TB) {
            pb0 = bval_t ? *(const float4*)(B + (long long)(bn + brow) * ldb + bk8) : f0;
            pb1 = bval_t ? *(const float4*)(B + (long long)(bn + brow) * ldb + bk8 + 4) : f0;
        } else {
            pb0 = bval_n0 ? *(const float4*)(B + (long long)bkr * ldb + bn + bn8) : f0;
            pb1 = bval_n1 ? *(const float4*)(B + (long long)bkr * ldb + bn + bn8 + 4) : f0;
        }
    }
    /* store stage 0 */
    {
        const float* af = (const float*)&pa0;
#pragma unroll
        for (int i = 0; i < 4; i++) As[0][ak8 + i][arow] = f2tf32(af[i]);
        af = (const float*)&pa1;
#pragma unroll
        for (int i = 0; i < 4; i++) As[0][ak8 + 4 + i][arow] = f2tf32(af[i]);
        if (TB) {
            const float* bf = (const float*)&pb0;
#pragma unroll
            for (int i = 0; i < 4; i++) Bs[0][bk8 + i][brow] = f2tf32(bf[i]);
            bf = (const float*)&pb1;
#pragma unroll
            for (int i = 0; i < 4; i++) Bs[0][bk8 + 4 + i][brow] = f2tf32(bf[i]);
        } else {
            const float* bf = (const float*)&pb0;
#pragma unroll
            for (int i = 0; i < 4; i++) Bs[0][bkr][bn8 + i] = f2tf32(bf[i]);
            bf = (const float*)&pb1;
#pragma unroll
            for (int i = 0; i < 4; i++) Bs[0][bkr][bn8 + 4 + i] = f2tf32(bf[i]);
        }
    }
    __syncthreads();

    float acc[4][4][4];
#pragma unroll
    for (int mt = 0; mt < 4; mt++)
#pragma unroll
        for (int nt = 0; nt < 4; nt++)
#pragma unroll
            for (int u = 0; u < 4; u++) acc[mt][nt][u] = 0.f;

    const int nst = K >> 4;
    for (int st = 0; st < nst; st++) {
        if (st + 1 < nst) {
            int kb = (st + 1) << 4;
            pa0 = *(const float4*)(Aptr + kb);
            pa1 = *(const float4*)(Aptr + kb + 4);
            if (TB) {
                pb0 = bval_t ? *(const float4*)(B + (long long)(bn + brow) * ldb + kb + bk8) : f0;
                pb1 = bval_t ? *(const float4*)(B + (long long)(bn + brow) * ldb + kb + bk8 + 4) : f0;
            } else {
                pb0 = bval_n0 ? *(const float4*)(B + (long long)(kb + bkr) * ldb + bn + bn8) : f0;
                pb1 = bval_n1 ? *(const float4*)(B + (long long)(kb + bkr) * ldb + bn + bn8 + 4) : f0;
            }
        }
        const int buf = st & 1;
#pragma unroll
        for (int ks = 0; ks < 2; ks++) {
            const int k8 = ks * 8;
            unsigned af[4][4], bf[4][2];
#pragma unroll
            for (int mt = 0; mt < 4; mt++) {
                int m = warpM * 64 + mt * 16 + g;
                af[mt][0] = As[buf][k8 + tg][m];
                af[mt][1] = As[buf][k8 + tg][m + 8];
                af[mt][2] = As[buf][k8 + tg + 4][m];
                af[mt][3] = As[buf][k8 + tg + 4][m + 8];
            }
#pragma unroll
            for (int nt = 0; nt < 4; nt++) {
                int n = warpN * 32 + nt * 8 + g;
                bf[nt][0] = Bs[buf][k8 + tg][n];
                bf[nt][1] = Bs[buf][k8 + tg + 4][n];
            }
#pragma unroll
            for (int mt = 0; mt < 4; mt++)
#pragma unroll
                for (int nt = 0; nt < 4; nt++)
                    mma_tf32(acc[mt][nt], af[mt], bf[nt]);
        }
        if (st + 1 < nst) {
            const int nb = (st + 1) & 1;
            const float* af = (const float*)&pa0;
#pragma unroll
            for (int i = 0; i < 4; i++) As[nb][ak8 + i][arow] = f2tf32(af[i]);
            af = (const float*)&pa1;
#pragma unroll
            for (int i = 0; i < 4; i++) As[nb][ak8 + 4 + i][arow] = f2tf32(af[i]);
            if (TB) {
                const float* bfp = (const float*)&pb0;
#pragma unroll
                for (int i = 0; i < 4; i++) Bs[nb][bk8 + i][brow] = f2tf32(bfp[i]);
                bfp = (const float*)&pb1;
#pragma unroll
                for (int i = 0; i < 4; i++) Bs[nb][bk8 + 4 + i][brow] = f2tf32(bfp[i]);
            } else {
                const float* bfp = (const float*)&pb0;
#pragma unroll
                for (int i = 0; i < 4; i++) Bs[nb][bkr][bn8 + i] = f2tf32(bfp[i]);
                bfp = (const float*)&pb1;
#pragma unroll
                for (int i = 0; i < 4; i++) Bs[nb][bkr][bn8 + 4 + i] = f2tf32(bfp[i]);
            }
        }
        __syncthreads();
    }

    /* ---- epilogue (mma fragment ownership: rows g/g+8, cols tg*2, tg*2+1) ---- */
#pragma unroll
    for (int mt = 0; mt < 4; mt++) {
        const int m0 = bm + warpM * 64 + mt * 16 + g;
        const int m1 = m0 + 8;
        float inv0 = 1.f, inv1 = 1.f;
        if (rscale) {
            inv0 = 1.f / rscale[(size_t)batch * M + m0];
            inv1 = 1.f / rscale[(size_t)batch * M + m1];
        }
        const float* pbr0 = nullptr;
        const float* pbr1 = nullptr;
        if (MODE == 3) {
            pbr0 = pbias + (size_t)batch * (NPn * NPn) + (size_t)(m0 >> 3) * NPn;
            pbr1 = pbias + (size_t)batch * (NPn * NPn) + (size_t)(m1 >> 3) * NPn;
        }
        float r0 = 0.f, r1 = 0.f;
#pragma unroll
        for (int nt = 0; nt < 4; nt++) {
            const int n = bn + warpN * 32 + nt * 8 + tg * 2;
            if (n < N) {
                float c0 = acc[mt][nt][0], c1 = acc[mt][nt][1];
                float c2 = acc[mt][nt][2], c3 = acc[mt][nt][3];
                if (bias) {
                    float2 bb = *(const float2*)&bias[n];
                    c0 += bb.x; c1 += bb.y; c2 += bb.x; c3 += bb.y;
                }
                if (MODE == 1) {
                    c0 = fmaxf(c0, 0.f); c1 = fmaxf(c1, 0.f);
                    c2 = fmaxf(c2, 0.f); c3 = fmaxf(c3, 0.f);
                }
                if (MODE == 3) {
                    float pb0v = pbr0[n >> 3], pb1v = pbr1[n >> 3];
                    c0 = softclamp_exp(c0 + pb0v);
                    c1 = softclamp_exp(c1 + pb0v);
                    c2 = softclamp_exp(c2 + pb1v);
                    c3 = softclamp_exp(c3 + pb1v);
                    r0 += c0 + c1; r1 += c2 + c3;
                }
                if (MODE == 4) {
                    c0 = __expf(c0); c1 = __expf(c1);
                    c2 = __expf(c2); c3 = __expf(c3);
                    r0 += c0 + c1; r1 += c2 + c3;
                }
                if (rscale) { c0 *= inv0; c1 *= inv0; c2 *= inv1; c3 *= inv1; }
                float2 w0, w1;
                if (MODE == 2) {
                    float2 o0 = *(const float2*)&C[(long long)m0 * ldc + n];
                    float2 o1 = *(const float2*)&C[(long long)m1 * ldc + n];
                    w0.x = c0 + o0.x; w0.y = c1 + o0.y;
                    w1.x = c2 + o1.x; w1.y = c3 + o1.y;
                } else {
                    w0.x = c0; w0.y = c1; w1.x = c2; w1.y = c3;
                }
                *(float2*)&C[(long long)m0 * ldc + n] = w0;
                *(float2*)&C[(long long)m1 * ldc + n] = w1;
            }
        }
        if (MODE == 3 || MODE == 4) {
            r0 += __shfl_xor_sync(0xffffffffu, r0, 1);
            r0 += __shfl_xor_sync(0xffffffffu, r0, 2);
            r1 += __shfl_xor_sync(0xffffffffu, r1, 1);
            r1 += __shfl_xor_sync(0xffffffffu, r1, 2);
            if (tg == 0) {
                atomicAdd(&rsum[(size_t)batch * M + m0], r0);
                atomicAdd(&rsum[(size_t)batch * M + m1], r1);
            }
        }
    }
}

/* ---------------- norms ---------------- */
__global__ void rmsnorm_k(const float* __restrict__ x, const float* __restrict__ w,
                          float* __restrict__ y, int cols)
{
    long long r = blockIdx.x;
    const float* xr = x + r * cols;
    float ss = 0.f;
    for (int c = threadIdx.x; c < cols; c += blockDim.x) { float v = xr[c]; ss += v * v; }
    ss = blockReduce<0>(ss);
    float inv = rsqrtf(ss / cols + EPS_RMS);
    for (int c = threadIdx.x; c < cols; c += blockDim.x)
        y[r * cols + c] = xr[c] * inv * w[c];
}

/* res += rmsnorm(x)*w1; if (w2) out = rmsnorm(res)*w2.  cols=768, 256 thr. */
__global__ void rmsnorm_add_norm_k(const float* __restrict__ x, const float* __restrict__ w1,
                                   float* __restrict__ res, const float* __restrict__ w2,
                                   float* __restrict__ out)
{
    long long r = blockIdx.x;
    const int cols = Dn;
    const float* xr = x + r * cols;
    float xv[3], rv[3];
    float ss = 0.f;
#pragma unroll
    for (int u = 0; u < 3; u++) {
        xv[u] = xr[threadIdx.x + u * 256];
        ss += xv[u] * xv[u];
    }
    ss = blockReduce<0>(ss);
    float inv = rsqrtf(ss / cols + EPS_RMS);
    float ss2 = 0.f;
#pragma unroll
    for (int u = 0; u < 3; u++) {
        int c = threadIdx.x + u * 256;
        float v = res[r * cols + c] + xv[u] * inv * w1[c];
        res[r * cols + c] = v;
        rv[u] = v;
        ss2 += v * v;
    }
    if (w2) {
        ss2 = blockReduce<0>(ss2);
        float inv2 = rsqrtf(ss2 / cols + EPS_RMS);
#pragma unroll
        for (int u = 0; u < 3; u++) {
            int c = threadIdx.x + u * 256;
            out[r * cols + c] = rv[u] * inv2 * w2[c];
        }
    }
}

/* ---------------- qkv post: per-head LayerNorm + scale + rotary ---------------- */
__global__ void qkv_post_k(const float* __restrict__ qkv,
                           const float* __restrict__ qn, const float* __restrict__ kn,
                           const float* __restrict__ vn,
                           float* __restrict__ q, float* __restrict__ k, float* __restrict__ v)
{
    int n = blockIdx.x, s = blockIdx.y, t = threadIdx.x;
    int len = (s == 9) ? 192 : 128;
    int off = (s < 8) ? s * 128 : (s == 8 ? 1024 : 1152);
    __shared__ float xs[192];
    float x = 0.f;
    if (t < len) x = qkv[(long long)n * NQKVn + off + t];
    float sum = blockReduce<0>(t < len ? x : 0.f);
    float sq  = blockReduce<0>(t < len ? x * x : 0.f);
    float mu = sum / len;
    float var = sq / len - mu * mu;
    float inv = rsqrtf(var + EPS_LN);
    float y = 0.f;
    if (t < len) {
        const float* w = (s < 8) ? qn : (s == 8 ? kn : vn);
        y = (x - mu) * inv * w[t];
        if (s < 8) y *= 0.125f;
    }
    if (s == 9) { if (t < 192) v[n * DVn + t] = y; return; }
    xs[t] = y;
    __syncthreads();
    if (t < 128) {
        int d2 = t & 63;
        float invf = (d2 == 0) ? 0.1f : 0.0f;
        float f = (float)n * invf;
        float c = cosf(f), si = sinf(f);
        float rh = (t < 64) ? -xs[t + 64] : xs[t - 64];
        float out = y * c + rh * si;
        if (s < 8) q[((size_t)s * SEQn + n) * DQKn + t] = out;
        else       k[n * DQKn + t] = out;
    }
}

/* ------------- pairwise bias: rms -> gelu -> [128->8], warp per (i,j) ------------- */
__global__ __launch_bounds__(256) void pb_kernel(
    const float* __restrict__ pair, const float* __restrict__ rw,
    const float* __restrict__ proj, float* __restrict__ pb)
{
    int warp = (blockIdx.x * blockDim.x + threadIdx.x) >> 5;   /* 0..65535 */
    int lane = threadIdx.x & 31;
    float4 x = *(const float4*)(pair + (size_t)warp * DPn + lane * 4);
    float ss = x.x * x.x + x.y * x.y + x.z * x.z + x.w * x.w;
#pragma unroll
    for (int off = 16; off > 0; off >>= 1)
        ss += __shfl_xor_sync(0xffffffffu, ss, off);
    float inv = rsqrtf(ss * (1.f / DPn) + EPS_RMS);
    float4 w4 = *(const float4*)(rw + lane * 4);
    float g[4];
    {
        float y0 = x.x * inv * w4.x, y1 = x.y * inv * w4.y;
        float y2 = x.z * inv * w4.z, y3 = x.w * inv * w4.w;
        g[0] = 0.5f * y0 * (1.f + erff(y0 * 0.70710678118654752f));
        g[1] = 0.5f * y1 * (1.f + erff(y1 * 0.70710678118654752f));
        g[2] = 0.5f * y2 * (1.f + erff(y2 * 0.70710678118654752f));
        g[3] = 0.5f * y3 * (1.f + erff(y3 * 0.70710678118654752f));
    }
    float p[8] = {0.f, 0.f, 0.f, 0.f, 0.f, 0.f, 0.f, 0.f};
#pragma unroll
    for (int c = 0; c < 4; c++) {
        const float* pr = proj + (size_t)(lane * 4 + c) * Hn;
        float4 a = *(const float4*)pr;
        float4 b = *(const float4*)(pr + 4);
        p[0] = fmaf(g[c], a.x, p[0]); p[1] = fmaf(g[c], a.y, p[1]);
        p[2] = fmaf(g[c], a.z, p[2]); p[3] = fmaf(g[c], a.w, p[3]);
        p[4] = fmaf(g[c], b.x, p[4]); p[5] = fmaf(g[c], b.y, p[5]);
        p[6] = fmaf(g[c], b.z, p[6]); p[7] = fmaf(g[c], b.w, p[7]);
    }
#pragma unroll
    for (int off = 16; off > 0; off >>= 1)
#pragma unroll
        for (int h = 0; h < 8; h++)
            p[h] += __shfl_xor_sync(0xffffffffu, p[h], off);
    if (lane < 8) {
        int i = warp >> 8, j = warp & 255;
        pb[((size_t)lane * NPn + i) * NPn + j] = p[lane];
    }
}

/* ---------------- host launcher ---------------- */
static inline void launch_gemm(bool tb, int mode, int M, int N, int K,
                               const float* A, int lda, long long sA,
                               const float* B, int ldb, long long sB,
                               float* C, int ldc, long long sC, int batch,
                               const float* bias, const float* pbias,
                               float* rsum, const float* rscale)
{
    dim3 g((N + 127) / 128, M / 128, batch), b(256);
    if (tb) {
        if (mode == 3)      gemm_tc<true, 3><<<g, b>>>(M, N, K, A, lda, sA, B, ldb, sB, C, ldc, sC, bias, pbias, rsum, rscale);
        else if (mode == 4) gemm_tc<true, 4><<<g, b>>>(M, N, K, A, lda, sA, B, ldb, sB, C, ldc, sC, bias, pbias, rsum, rscale);
        else                gemm_tc<true, 0><<<g, b>>>(M, N, K, A, lda, sA, B, ldb, sB, C, ldc, sC, bias, pbias, rsum, rscale);
    } else {
        if (mode == 1)      gemm_tc<false, 1><<<g, b>>>(M, N, K, A, lda, sA, B, ldb, sB, C, ldc, sC, bias, pbias, rsum, rscale);
        else if (mode == 2) gemm_tc<false, 2><<<g, b>>>(M, N, K, A, lda, sA, B, ldb, sB, C, ldc, sC, bias, pbias, rsum, rscale);
        else                gemm_tc<false, 0><<<g, b>>>(M, N, K, A, lda, sA, B, ldb, sB, C, ldc, sC, bias, pbias, rsum, rscale);
    }
}

extern "C" void kernel_launch(void* const* d_in, const int* in_sizes, int n_in,
                              void* d_out, int out_size)
{
    (void)in_sizes; (void)n_in; (void)out_size;
    const float* in_single = (const float*)d_in[0];
    const float* in_pair   = (const float*)d_in[1];
    const float* W_attn_pre  = (const float*)d_in[2];
    const float* W_attn_post = (const float*)d_in[3];
    const float* W_qkv  = (const float*)d_in[4];
    const float* W_qn   = (const float*)d_in[5];
    const float* W_kn   = (const float*)d_in[6];
    const float* W_vn   = (const float*)d_in[7];
    const float* W_brms = (const float*)d_in[8];
    const float* W_bproj= (const float*)d_in[9];
    const float* W_out  = (const float*)d_in[10];
    const float* W_ffpre = (const float*)d_in[11];
    const float* W_ffpost= (const float*)d_in[12];
    const float* W_ff1  = (const float*)d_in[13];
    const float* B_ff1  = (const float*)d_in[14];
    const float* W_ff2  = (const float*)d_in[15];
    const float* B_ff2  = (const float*)d_in[16];
    const float* W_ppre = (const float*)d_in[17];
    const float* W_pqk  = (const float*)d_in[18];
    const float* W_pv   = (const float*)d_in[19];
    const float* B_pv   = (const float*)d_in[20];
    const float* W_pffpre = (const float*)d_in[21];
    const float* W_pff1 = (const float*)d_in[22];
    const float* B_pff1 = (const float*)d_in[23];
    const float* W_pff2 = (const float*)d_in[24];
    const float* B_pff2 = (const float*)d_in[25];

    float *xn, *qkv, *q, *k, *v, *sim, *pb, *ao, *t1, *rsum;
    float *pxn, *pqk, *pv, *psim, *prsum, *pt;
    cudaGetSymbolAddress((void**)&xn, g_xn);
    cudaGetSymbolAddress((void**)&qkv, g_qkv);
    cudaGetSymbolAddress((void**)&q, g_q);
    cudaGetSymbolAddress((void**)&k, g_k);
    cudaGetSymbolAddress((void**)&v, g_v);
    cudaGetSymbolAddress((void**)&sim, g_sim);
    cudaGetSymbolAddress((void**)&pb, g_pb);
    cudaGetSymbolAddress((void**)&ao, g_ao);
    cudaGetSymbolAddress((void**)&t1, g_t1);
    cudaGetSymbolAddress((void**)&rsum, g_rsum);
    cudaGetSymbolAddress((void**)&pxn, g_pxn);
    cudaGetSymbolAddress((void**)&pqk, g_pqk);
    cudaGetSymbolAddress((void**)&pv, g_pv);
    cudaGetSymbolAddress((void**)&psim, g_psim);
    cudaGetSymbolAddress((void**)&prsum, g_prsum);
    cudaGetSymbolAddress((void**)&pt, g_pt);

    /* residual streams live directly in d_out: [single | pairwise] */
    float* single = (float*)d_out;
    float* pair   = (float*)d_out + (size_t)SEQn * Dn;
    cudaMemcpyAsync(single, in_single, (size_t)SEQn * Dn * 4, cudaMemcpyDeviceToDevice);
    cudaMemcpyAsync(pair, in_pair, (size_t)NPn * NPn * DPn * 4, cudaMemcpyDeviceToDevice);

    /* xn = rmsnorm(single, attn_pre[0]) for the first layer */
    rmsnorm_k<<<SEQn, 256>>>(single, W_attn_pre, xn, Dn);

    for (int i = 0; i < 4; i++) {
        /* ---- single-track attention ---- */
        launch_gemm(false, 0, SEQn, NQKVn, Dn, xn, Dn, 0,
                    W_qkv + (long long)i * Dn * NQKVn, NQKVn, 0, qkv, NQKVn, 0, 1,
                    nullptr, nullptr, nullptr, nullptr);
        qkv_post_k<<<dim3(SEQn, 10), 192>>>(qkv, W_qn + i * DQKn, W_kn + i * DQKn,
                                            W_vn + i * DVn, q, k, v);
        pb_kernel<<<NPn * NPn / 8, 256>>>(pair, W_brms + i * DPn, W_bproj + i * DPn * Hn, pb);
        zero_k<<<(Hn * SEQn + 255) / 256, 256>>>(rsum, Hn * SEQn);
        /* P = exp(softclamp(qk^T + pb)), rowsums accumulated */
        launch_gemm(true, 3, SEQn, SEQn, DQKn, q, DQKn, (long long)SEQn * DQKn,
                    k, DQKn, 0, sim, SEQn, (long long)SEQn * SEQn, Hn,
                    nullptr, pb, rsum, nullptr);
        /* O = (P/rowsum) V */
        launch_gemm(false, 0, SEQn, DVn, SEQn, sim, SEQn, (long long)SEQn * SEQn,
                    v, DVn, 0, ao, Hn * DVn, DVn, Hn,
                    nullptr, nullptr, nullptr, rsum);
        launch_gemm(false, 0, SEQn, Dn, Hn * DVn, ao, Hn * DVn, 0,
                    W_out + (long long)i * Hn * DVn * Dn, Dn, 0, t1, Dn, 0, 1,
                    nullptr, nullptr, nullptr, nullptr);
        /* single += rms(t1)*attn_post; xn = rms(single)*ff_pre */
        rmsnorm_add_norm_k<<<SEQn, 256>>>(t1, W_attn_post + i * Dn, single,
                                          W_ffpre + i * Dn, xn);

        /* ---- single-track FF ---- */
        launch_gemm(false, 1, SEQn, FFIn, Dn, xn, Dn, 0,
                    W_ff1 + (long long)i * Dn * FFIn, FFIn, 0, ao, FFIn, 0, 1,
                    B_ff1 + i * FFIn, nullptr, nullptr, nullptr);
        launch_gemm(false, 0, SEQn, Dn, FFIn, ao, FFIn, 0,
                    W_ff2 + (long long)i * FFIn * Dn, Dn, 0, t1, Dn, 0, 1,
                    B_ff2 + i * Dn, nullptr, nullptr, nullptr);
        /* single += rms(t1)*ff_post; xn = rms(single)*attn_pre[i+1] (if any) */
        rmsnorm_add_norm_k<<<SEQn, 256>>>(t1, W_ffpost + i * Dn, single,
                                          (i < 3) ? W_attn_pre + (i + 1) * Dn : nullptr, xn);

        /* ---- pairwise track (layers 0, 2) ---- */
        if ((i & 1) == 0) {
            int j = i / 2;
            rmsnorm_k<<<NPn * NPn, 128>>>(pair, W_ppre + j * DPn, pxn, DPn);
            launch_gemm(false, 0, NPn * NPn, 2 * DPn, DPn, pxn, DPn, 0,
                        W_pqk + (long long)j * DPn * 2 * DPn, 2 * DPn, 0,
                        pqk, 2 * DPn, 0, 1, nullptr, nullptr, nullptr, nullptr);
            launch_gemm(false, 0, NPn * NPn, DPn, DPn, pxn, DPn, 0,
                        W_pv + (long long)j * DPn * DPn, DPn, 0,
                        pv, DPn, 0, 1, B_pv + j * DPn, nullptr, nullptr, nullptr);
            zero_k<<<(NPn * NPn + 255) / 256, 256>>>(prsum, NPn * NPn);
            launch_gemm(true, 4, NPn, NPn, DPn, pqk, 2 * DPn, (long long)NPn * 2 * DPn,
                        pqk + DPn, 2 * DPn, (long long)NPn * 2 * DPn,
                        psim, NPn, (long long)NPn * NPn, NPn,
                        nullptr, nullptr, prsum, nullptr);
            /* pair += (P/rowsum) V */
            launch_gemm(false, 2, NPn, DPn, NPn, psim, NPn, (long long)NPn * NPn,
                        pv, DPn, (long long)NPn * DPn,
                        pair, DPn, (long long)NPn * DPn, NPn,
                        nullptr, nullptr, nullptr, prsum);
            rmsnorm_k<<<NPn * NPn, 128>>>(pair, W_pffpre + j * DPn, pxn, DPn);
            launch_gemm(false, 1, NPn * NPn, DPIn, DPn, pxn, DPn, 0,
                        W_pff1 + (long long)j * DPn * DPIn, DPIn, 0,
                        pt, DPIn, 0, 1, B_pff1 + j * DPIn, nullptr, nullptr, nullptr);
            /* pair += ff2(pt) */
            launch_gemm(false, 2, NPn * NPn, DPn, DPIn, pt, DPIn, 0,
                        W_pff2 + (long long)j * DPIn * DPn, DPn, 0,
                        pair, DPn, 0, 1, B_pff2 + j * DPn, nullptr, nullptr, nullptr);
        }
    }
}